// round 1
// baseline (speedup 1.0000x reference)
#include <cuda_runtime.h>

// y[t, f] = x[t, f] * w[f] + b[f]
// x: [8192, 4096] f32, w/b: [4096] f32, out: [8192, 4096] f32
// Pure HBM stream: 256 MiB total traffic. float4-vectorized.

static constexpr int TOKENS = 8192;
static constexpr int FEATURES = 4096;
static constexpr int F4_PER_ROW = FEATURES / 4;          // 1024
static constexpr int TOTAL_F4 = TOKENS * F4_PER_ROW;     // 8,388,608

__global__ void __launch_bounds__(256) one_to_one_kernel(
    const float4* __restrict__ x,
    const float4* __restrict__ w,
    const float4* __restrict__ b,
    float4* __restrict__ out)
{
    int i = blockIdx.x * blockDim.x + threadIdx.x;
    if (i >= TOTAL_F4) return;

    int c = i & (F4_PER_ROW - 1);   // column in float4 units

    float4 xv = x[i];
    float4 wv = __ldg(&w[c]);
    float4 bv = __ldg(&b[c]);

    float4 r;
    r.x = fmaf(xv.x, wv.x, bv.x);
    r.y = fmaf(xv.y, wv.y, bv.y);
    r.z = fmaf(xv.z, wv.z, bv.z);
    r.w = fmaf(xv.w, wv.w, bv.w);

    out[i] = r;
}

extern "C" void kernel_launch(void* const* d_in, const int* in_sizes, int n_in,
                              void* d_out, int out_size)
{
    const float4* x = (const float4*)d_in[0];
    const float4* w = (const float4*)d_in[1];
    const float4* b = (const float4*)d_in[2];
    float4* out = (float4*)d_out;

    const int threads = 256;
    const int blocks = (TOTAL_F4 + threads - 1) / threads;  // 32768
    one_to_one_kernel<<<blocks, threads>>>(x, w, b, out);
}